// round 2
// baseline (speedup 1.0000x reference)
#include <cuda_runtime.h>
#include <cuda_bf16.h>
#include <math.h>
#include <stdint.h>

#define BATCH 256
#define NPOSE 135
#define TTOT  144
#define ENCS  119
#define TGT   24
#define RNN   1024
#define GATES 4096
#define KDEC  1280
#define MZ    (ENCS*BATCH)   /* 30464 */

// ---------------- device scratch ----------------
__device__ float g_Z[MZ*256];           // encoder z_t (tf32-rounded), time-major rows t*256+b
__device__ float g_posesPad[MZ*256];    // time-major padded poses
__device__ float g_WinPad[256*256];     // W_in padded [256 x 256]
__device__ float g_Wcat[GATES*KDEC];    // [W_hh | W_ih] rows of 1280
__device__ float g_Wr1p[1024*1024];     // W_r1 padded 960->1024 rows
__device__ float g_br1p[1024];
__device__ float g_Wr2p[256*1024];      // W_r2 padded [256 x 1024]
__device__ float g_br2p[256];
__device__ float g_biasg[GATES];        // b_ih + b_hh
__device__ float g_hzA[BATCH*RNN];      // h double buffer A
__device__ float g_hzB[BATCH*RNN];      // h double buffer B
__device__ float g_c[BATCH*RNN];        // cell state
__device__ float g_r1[BATCH*1024];      // relu hidden
__device__ float g_s[BATCH*256];        // decoder feedback state (tf32-rounded)
__device__ float g_zd[BATCH*256];       // decoder z

__device__ __forceinline__ float tf32r(float x){
    unsigned u; asm("cvt.rna.tf32.f32 %0, %1;" : "=r"(u) : "f"(x));
    return __uint_as_float(u);
}
__device__ __forceinline__ void cpa16(void* dst, const void* src){
    unsigned d = (unsigned)__cvta_generic_to_shared(dst);
    asm volatile("cp.async.cg.shared.global [%0], [%1], 16;" :: "r"(d), "l"(src));
}
__device__ __forceinline__ void mma8(float* d, const unsigned* a, const unsigned* b){
    asm volatile("mma.sync.aligned.m16n8k8.row.col.f32.tf32.tf32.f32 "
        "{%0,%1,%2,%3},{%4,%5,%6,%7},{%8,%9},{%0,%1,%2,%3};"
        : "+f"(d[0]),"+f"(d[1]),"+f"(d[2]),"+f"(d[3])
        : "r"(a[0]),"r"(a[1]),"r"(a[2]),"r"(a[3]),"r"(b[0]),"r"(b[1]));
}

// ---------------- prep: pack/pad weights (tf32-rounded), zero state ----------------
#define N_WCAT (GATES*KDEC)
#define N_WR1  (1024*1024)
#define N_WR2  (256*1024)
#define N_HZ   (2*BATCH*RNN)
#define N_C    (BATCH*RNN)
#define N_PP   (MZ*256)
#define N_WIN  (256*256)
#define NTOT   (N_WCAT + N_WR1 + 1024 + N_WR2 + 256 + GATES + N_HZ + N_C + N_PP + N_WIN)

__global__ void prep_kernel(
    const float* __restrict__ poses, const float* __restrict__ W_in,
    const float* __restrict__ W_ih,  const float* __restrict__ W_hh,
    const float* __restrict__ b_ih,  const float* __restrict__ b_hh,
    const float* __restrict__ W_r1,  const float* __restrict__ b_r1,
    const float* __restrict__ W_r2,  const float* __restrict__ b_r2)
{
    int i = blockIdx.x * 256 + threadIdx.x;
    if (i < N_WCAT){ int n=i/KDEC, k=i%KDEC;
        g_Wcat[i] = tf32r(k < 1024 ? W_hh[n*1024+k] : W_ih[n*256 + (k-1024)]); return; }
    i -= N_WCAT;
    if (i < N_WR1){ int n=i>>10, k=i&1023;
        g_Wr1p[i] = (n < 960) ? tf32r(W_r1[n*1024+k]) : 0.f; return; }
    i -= N_WR1;
    if (i < 1024){ g_br1p[i] = (i < 960) ? b_r1[i] : 0.f; return; }
    i -= 1024;
    if (i < N_WR2){ int n=i>>10, k=i&1023;
        g_Wr2p[i] = (n < NPOSE && k < 960) ? tf32r(W_r2[n*960+k]) : 0.f; return; }
    i -= N_WR2;
    if (i < 256){ g_br2p[i] = (i < NPOSE) ? b_r2[i] : 0.f; return; }
    i -= 256;
    if (i < GATES){ g_biasg[i] = b_ih[i] + b_hh[i]; return; }
    i -= GATES;
    if (i < N_HZ){ if (i < BATCH*RNN) g_hzA[i] = 0.f; else g_hzB[i-BATCH*RNN] = 0.f; return; }
    i -= N_HZ;
    if (i < N_C){ g_c[i] = 0.f; return; }
    i -= N_C;
    if (i < N_PP){ int m=i>>8, k=i&255; int b=m&255, t=m>>8;
        g_posesPad[i] = (k < NPOSE) ? tf32r(poses[((size_t)b*TTOT + t)*NPOSE + k]) : 0.f; return; }
    i -= N_PP;
    if (i < N_WIN){ int n=i>>8, k=i&255;
        g_WinPad[i] = (k < NPOSE) ? tf32r(W_in[n*NPOSE+k]) : 0.f; return; }
}

// ---------------- tf32 GEMM, BM=64 BN=64 BK=32, fused epilogues ----------------
// A operand: cols <1024 from A (lda), cols >=1024 from A2 (lda2)   [concat trick]
// mode 0: LSTM gates (fold N layout), cell update, write h (tf32) + c
// mode 2: relu + tf32 store
// mode 3: + bias + optional residual; store s (tf32) and optionally predictions (fp32)
// mode 4: + bias, tf32 store
__global__ void __launch_bounds__(256, 2) gemm_tf32(
    const float* __restrict__ A,  int lda,
    const float* __restrict__ A2, int lda2,
    const float* __restrict__ Bw, int ldb,
    int K, int mode, int fold,
    const float* __restrict__ addvec,
    float* __restrict__ outp, int out_ld,
    float* __restrict__ cbuf, float* __restrict__ hbuf, int h_ld,
    const float* __restrict__ residp, int resid_stride,
    float* __restrict__ predout, int tstep)
{
    __shared__ float As[2][64*36];
    __shared__ float Bs[2][64*36];
    const int tid  = threadIdx.x;
    const int lane = tid & 31;
    const int wid  = tid >> 5;
    const int wm   = wid >> 2;   // 0..1
    const int wn   = wid & 3;    // 0..3
    const int m0   = blockIdx.x * 64;
    const int bn   = blockIdx.y;

    const int r0 = tid >> 3;            // 0..31
    const int c0 = (tid & 7) << 2;      // 0,4,..,28
    const int r1 = r0 + 32;

    const int ng0 = fold ? ((r0 >> 4) * 1024 + bn * 16 + (r0 & 15)) : (bn * 64 + r0);
    const int ng1 = fold ? ((r1 >> 4) * 1024 + bn * 16 + (r1 & 15)) : (bn * 64 + r1);
    const float* bS0 = Bw + (size_t)ng0 * ldb + c0;
    const float* bS1 = Bw + (size_t)ng1 * ldb + c0;

    float acc[2][2][4];
    #pragma unroll
    for (int a=0;a<2;a++)
        #pragma unroll
        for (int b=0;b<2;b++)
            #pragma unroll
            for (int e=0;e<4;e++) acc[a][b][e] = 0.f;

    const int nk = K >> 5;

    // prologue (stage 0)
    {
        int k = c0;
        const float* a0 = (k < 1024) ? A + (size_t)(m0+r0)*lda + k : A2 + (size_t)(m0+r0)*lda2 + (k-1024);
        const float* a1 = (k < 1024) ? A + (size_t)(m0+r1)*lda + k : A2 + (size_t)(m0+r1)*lda2 + (k-1024);
        cpa16(&As[0][r0*36 + c0], a0);
        cpa16(&As[0][r1*36 + c0], a1);
        cpa16(&Bs[0][r0*36 + c0], bS0);
        cpa16(&Bs[0][r1*36 + c0], bS1);
    }
    asm volatile("cp.async.commit_group;");

    for (int ks = 0; ks < nk; ks++){
        if (ks + 1 < nk){
            const int buf = (ks + 1) & 1;
            const int k0  = (ks + 1) << 5;
            int k = k0 + c0;
            const float* a0 = (k < 1024) ? A + (size_t)(m0+r0)*lda + k : A2 + (size_t)(m0+r0)*lda2 + (k-1024);
            const float* a1 = (k < 1024) ? A + (size_t)(m0+r1)*lda + k : A2 + (size_t)(m0+r1)*lda2 + (k-1024);
            cpa16(&As[buf][r0*36 + c0], a0);
            cpa16(&As[buf][r1*36 + c0], a1);
            cpa16(&Bs[buf][r0*36 + c0], bS0 + k0);
            cpa16(&Bs[buf][r1*36 + c0], bS1 + k0);
        }
        asm volatile("cp.async.commit_group;");
        asm volatile("cp.async.wait_group 1;");
        __syncthreads();

        const float* Ab = &As[ks & 1][0];
        const float* Bb = &Bs[ks & 1][0];
        const int tg = lane >> 2, ti = lane & 3;
        #pragma unroll
        for (int kk = 0; kk < 32; kk += 8){
            unsigned af[2][4], bf[2][2];
            #pragma unroll
            for (int mi = 0; mi < 2; mi++){
                int rr = wm*32 + mi*16 + tg;
                af[mi][0] = __float_as_uint(Ab[rr*36 + kk + ti]);
                af[mi][1] = __float_as_uint(Ab[(rr+8)*36 + kk + ti]);
                af[mi][2] = __float_as_uint(Ab[rr*36 + kk + 4 + ti]);
                af[mi][3] = __float_as_uint(Ab[(rr+8)*36 + kk + 4 + ti]);
            }
            #pragma unroll
            for (int ni = 0; ni < 2; ni++){
                int rr = wn*16 + ni*8 + tg;
                bf[ni][0] = __float_as_uint(Bb[rr*36 + kk + ti]);
                bf[ni][1] = __float_as_uint(Bb[rr*36 + kk + 4 + ti]);
            }
            #pragma unroll
            for (int mi = 0; mi < 2; mi++)
                #pragma unroll
                for (int ni = 0; ni < 2; ni++)
                    mma8(acc[mi][ni], af[mi], bf[ni]);
        }
        __syncthreads();
    }

    if (mode == 0){
        // stage gates (+bias) in smem, then fused cell update
        float* Gs = &As[0][0];    // 64 x 64, stride 68 (fits in 2*2304 floats)
        #pragma unroll
        for (int mi = 0; mi < 2; mi++)
            #pragma unroll
            for (int ni = 0; ni < 2; ni++)
                #pragma unroll
                for (int e = 0; e < 4; e++){
                    int rl = wm*32 + mi*16 + (lane>>2) + ((e>>1)<<3);
                    int cl = wn*16 + ni*8 + ((lane&3)<<1) + (e&1);
                    float v = acc[mi][ni][e];
                    int gcol = (cl>>4)*1024 + bn*16 + (cl&15);
                    v += addvec[gcol];
                    Gs[rl*68 + cl] = v;
                }
        __syncthreads();
        for (int e2 = tid; e2 < 64*16; e2 += 256){
            int mr = e2 >> 4, jl = e2 & 15;
            float xi = Gs[mr*68 + jl];
            float xf = Gs[mr*68 + 16 + jl];
            float xg = Gs[mr*68 + 32 + jl];
            float xo = Gs[mr*68 + 48 + jl];
            float ig = 1.f/(1.f+expf(-xi));
            float fg = 1.f/(1.f+expf(-xf));
            float gg = tanhf(xg);
            float og = 1.f/(1.f+expf(-xo));
            int mg = m0 + mr;
            int j  = bn*16 + jl;
            float cn = fg * cbuf[mg*RNN + j] + ig*gg;
            cbuf[mg*RNN + j] = cn;
            hbuf[(size_t)mg*h_ld + j] = tf32r(og * tanhf(cn));
        }
    } else {
        #pragma unroll
        for (int mi = 0; mi < 2; mi++)
            #pragma unroll
            for (int ni = 0; ni < 2; ni++)
                #pragma unroll
                for (int e = 0; e < 4; e++){
                    int rl = wm*32 + mi*16 + (lane>>2) + ((e>>1)<<3);
                    int cl = wn*16 + ni*8 + ((lane&3)<<1) + (e&1);
                    int mg = m0 + rl;
                    int ng = bn*64 + cl;
                    float v = acc[mi][ni][e];
                    if (addvec) v += addvec[ng];
                    if (mode == 2){
                        outp[(size_t)mg*out_ld + ng] = tf32r(fmaxf(v, 0.f));
                    } else if (mode == 4){
                        outp[(size_t)mg*out_ld + ng] = tf32r(v);
                    } else { // mode 3
                        if (residp != nullptr && ng < NPOSE)
                            v += residp[(size_t)mg*resid_stride + ng];
                        outp[mg*256 + ng] = tf32r(v);
                        if (predout != nullptr && ng < NPOSE)
                            predout[((size_t)mg*TGT + tstep)*NPOSE + ng] = v;
                    }
                }
    }
}

// ---------------- host launch sequence (graph-capturable) ----------------
extern "C" void kernel_launch(void* const* d_in, const int* in_sizes, int n_in,
                              void* d_out, int out_size)
{
    const float* poses = (const float*)d_in[0];
    const float* W_in  = (const float*)d_in[1];
    const float* b_in  = (const float*)d_in[2];
    const float* W_ih  = (const float*)d_in[3];
    const float* W_hh  = (const float*)d_in[4];
    const float* b_ih  = (const float*)d_in[5];
    const float* b_hh  = (const float*)d_in[6];
    const float* W_r1  = (const float*)d_in[7];
    const float* b_r1  = (const float*)d_in[8];
    const float* W_r2  = (const float*)d_in[9];
    const float* b_r2  = (const float*)d_in[10];
    float* out = (float*)d_out;

    float *pZ,*pPP,*pWin,*pWcat,*pWr1,*pbr1,*pWr2,*pbr2,*pbg,*pA,*pB,*pc,*pr1,*ps,*pzd;
    cudaGetSymbolAddress((void**)&pZ,    g_Z);
    cudaGetSymbolAddress((void**)&pPP,   g_posesPad);
    cudaGetSymbolAddress((void**)&pWin,  g_WinPad);
    cudaGetSymbolAddress((void**)&pWcat, g_Wcat);
    cudaGetSymbolAddress((void**)&pWr1,  g_Wr1p);
    cudaGetSymbolAddress((void**)&pbr1,  g_br1p);
    cudaGetSymbolAddress((void**)&pWr2,  g_Wr2p);
    cudaGetSymbolAddress((void**)&pbr2,  g_br2p);
    cudaGetSymbolAddress((void**)&pbg,   g_biasg);
    cudaGetSymbolAddress((void**)&pA,    g_hzA);
    cudaGetSymbolAddress((void**)&pB,    g_hzB);
    cudaGetSymbolAddress((void**)&pc,    g_c);
    cudaGetSymbolAddress((void**)&pr1,   g_r1);
    cudaGetSymbolAddress((void**)&ps,    g_s);
    cudaGetSymbolAddress((void**)&pzd,   g_zd);
    float* hz[2] = {pA, pB};

    // 1) pack/pad/zero
    prep_kernel<<<NTOT/256, 256>>>(poses, W_in, W_ih, W_hh, b_ih, b_hh, W_r1, b_r1, W_r2, b_r2);

    // 2) Z = posesPad @ WinPad^T + b_in   [30464 x 256], tf32-rounded store
    gemm_tf32<<<dim3(MZ/64, 4), 256>>>(pPP, 256, pPP, 256, pWin, 256, 256, 4, 0,
        b_in, pZ, 256, nullptr, nullptr, 0, nullptr, 0, nullptr, 0);

    // 3) encoder: 119 fused steps, gates = [h | z_t] @ Wcat^T + biasg
    int p = 0;
    for (int t = 0; t < ENCS; t++){
        gemm_tf32<<<dim3(4, 64), 256>>>(hz[p], 1024, pZ + (size_t)t*256*256, 256,
            pWcat, KDEC, KDEC, 0, 1, pbg, nullptr, 0, pc, hz[p^1], 1024,
            nullptr, 0, nullptr, 0);
        p ^= 1;
    }

    // 4) encoder-final head: s0 = relu(h@Wr1+b)@Wr2 + b + poses[:,118,:]
    gemm_tf32<<<dim3(4, 16), 256>>>(hz[p], 1024, hz[p], 1024, pWr1, 1024, 1024, 2, 0,
        pbr1, pr1, 1024, nullptr, nullptr, 0, nullptr, 0, nullptr, 0);
    gemm_tf32<<<dim3(4, 4), 256>>>(pr1, 1024, pr1, 1024, pWr2, 1024, 1024, 3, 0,
        pbr2, ps, 256, nullptr, nullptr, 0, poses + 118*NPOSE, TTOT*NPOSE, nullptr, 0);

    // 5) decoder: 24 autoregressive steps
    for (int t = 0; t < TGT; t++){
        // z = s @ W_in^T + b_in
        gemm_tf32<<<dim3(4, 4), 256>>>(ps, 256, ps, 256, pWin, 256, 256, 4, 0,
            b_in, pzd, 256, nullptr, nullptr, 0, nullptr, 0, nullptr, 0);
        // gates = [h | z] @ Wcat^T + biasg ; cell update ; new h
        gemm_tf32<<<dim3(4, 64), 256>>>(hz[p], 1024, pzd, 256,
            pWcat, KDEC, KDEC, 0, 1, pbg, nullptr, 0, pc, hz[p^1], 1024,
            nullptr, 0, nullptr, 0);
        p ^= 1;
        // r1 = relu(h @ Wr1^T + b)
        gemm_tf32<<<dim3(4, 16), 256>>>(hz[p], 1024, hz[p], 1024, pWr1, 1024, 1024, 2, 0,
            pbr1, pr1, 1024, nullptr, nullptr, 0, nullptr, 0, nullptr, 0);
        // s = r1 @ Wr2^T + b (+resid at t=0) ; predictions
        gemm_tf32<<<dim3(4, 4), 256>>>(pr1, 1024, pr1, 1024, pWr2, 1024, 1024, 3, 0,
            pbr2, ps, 256, nullptr, nullptr, 0,
            (t == 0) ? (poses + 119*NPOSE) : nullptr, TTOT*NPOSE, out, t);
    }
}

// round 3
// speedup vs baseline: 1.6922x; 1.6922x over previous
#include <cuda_runtime.h>
#include <cuda_bf16.h>
#include <math.h>
#include <stdint.h>

#define BATCH 256
#define NPOSE 135
#define TTOT  144
#define ENCS  119
#define TGT   24
#define RNN   1024
#define GATES 4096
#define KDEC  1280
#define MZ    (ENCS*BATCH)   /* 30464 */

#define NCTA    128
#define SMEM_HALVES (3*13824)          /* 3 stages x (A 64x72 + B 128x72) */
#define SMEM_BYTES  (SMEM_HALVES*2)    /* 82944 */

// ---------------- device scratch (uint4-backed for 16B alignment) ----------------
__device__ uint4 g_P_[MZ*256/8];        // poses padded, bf16, time-major [t*256+b][256]
__device__ uint4 g_Z_[MZ*256/8];        // encoder z, bf16
__device__ uint4 g_Win_[256*256/8];     // W_in padded, bf16
__device__ uint4 g_Wcat_[GATES*KDEC/8]; // [W_hh | W_ih], bf16
__device__ uint4 g_Wr1_[1024*1024/8];   // W_r1 padded (960->1024 rows), bf16
__device__ uint4 g_Wr2_[256*1024/8];    // W_r2 padded [256x1024], bf16
__device__ uint4 g_h0_[BATCH*RNN/8];    // h ping, bf16
__device__ uint4 g_h1_[BATCH*RNN/8];    // h pong, bf16
__device__ uint4 g_r1_[BATCH*1024/8];   // relu hidden, bf16
__device__ uint4 g_s_[BATCH*256/8];     // decoder feedback, bf16
__device__ uint4 g_zd_[BATCH*256/8];    // decoder z, bf16
__device__ float g_c[BATCH*RNN];        // cell state fp32
__device__ float g_biasg[GATES];        // b_ih + b_hh
__device__ float g_br1[1024];
__device__ float g_br2[256];
__device__ unsigned g_bar;

__device__ __forceinline__ void cpa16(void* dst, const void* src){
    unsigned d = (unsigned)__cvta_generic_to_shared(dst);
    asm volatile("cp.async.cg.shared.global [%0], [%1], 16;" :: "r"(d), "l"(src));
}
__device__ __forceinline__ void mma16(float* d, const unsigned* a, const unsigned* b){
    asm volatile("mma.sync.aligned.m16n8k16.row.col.f32.bf16.bf16.f32 "
        "{%0,%1,%2,%3},{%4,%5,%6,%7},{%8,%9},{%0,%1,%2,%3};"
        : "+f"(d[0]),"+f"(d[1]),"+f"(d[2]),"+f"(d[3])
        : "r"(a[0]),"r"(a[1]),"r"(a[2]),"r"(a[3]),"r"(b[0]),"r"(b[1]));
}
__device__ __forceinline__ unsigned ld32s(const __nv_bfloat16* p){
    return *(const unsigned*)p;
}

// ---------------- prep: pack/pad weights to bf16, zero state, reset barrier ----------------
#define N_WCAT (GATES*KDEC)
#define N_WR1  (1024*1024)
#define N_WR2  (256*1024)
#define N_H2C  (3*BATCH*RNN)
#define N_PP   (MZ*256)
#define N_WIN  (256*256)
#define NTOT   (N_WCAT + N_WR1 + 1024 + N_WR2 + 256 + GATES + N_H2C + N_PP + N_WIN)

__global__ void prep_kernel(
    const float* __restrict__ poses, const float* __restrict__ W_in,
    const float* __restrict__ W_ih,  const float* __restrict__ W_hh,
    const float* __restrict__ b_ih,  const float* __restrict__ b_hh,
    const float* __restrict__ W_r1,  const float* __restrict__ b_r1,
    const float* __restrict__ W_r2,  const float* __restrict__ b_r2)
{
    long long i = (long long)blockIdx.x * 256 + threadIdx.x;
    if (i == 0) g_bar = 0;
    if (i >= NTOT) return;
    __nv_bfloat16* P   = (__nv_bfloat16*)g_P_;
    __nv_bfloat16* Win = (__nv_bfloat16*)g_Win_;
    __nv_bfloat16* Wc  = (__nv_bfloat16*)g_Wcat_;
    __nv_bfloat16* W1  = (__nv_bfloat16*)g_Wr1_;
    __nv_bfloat16* W2  = (__nv_bfloat16*)g_Wr2_;
    __nv_bfloat16* H0  = (__nv_bfloat16*)g_h0_;
    __nv_bfloat16* H1  = (__nv_bfloat16*)g_h1_;

    if (i < N_WCAT){ int n=(int)(i/KDEC), k=(int)(i%KDEC);
        Wc[i] = __float2bfloat16(k < 1024 ? W_hh[(size_t)n*1024+k] : W_ih[(size_t)n*256 + (k-1024)]); return; }
    i -= N_WCAT;
    if (i < N_WR1){ int n=(int)(i>>10), k=(int)(i&1023);
        W1[i] = __float2bfloat16((n < 960) ? W_r1[(size_t)n*1024+k] : 0.f); return; }
    i -= N_WR1;
    if (i < 1024){ g_br1[i] = (i < 960) ? b_r1[i] : 0.f; return; }
    i -= 1024;
    if (i < N_WR2){ int n=(int)(i>>10), k=(int)(i&1023);
        W2[i] = __float2bfloat16((n < NPOSE && k < 960) ? W_r2[(size_t)n*960+k] : 0.f); return; }
    i -= N_WR2;
    if (i < 256){ g_br2[i] = (i < NPOSE) ? b_r2[i] : 0.f; return; }
    i -= 256;
    if (i < GATES){ g_biasg[i] = b_ih[i] + b_hh[i]; return; }
    i -= GATES;
    if (i < N_H2C){
        if (i < BATCH*RNN) H0[i] = __float2bfloat16(0.f);
        else if (i < 2*BATCH*RNN) H1[i-BATCH*RNN] = __float2bfloat16(0.f);
        else g_c[i-2*BATCH*RNN] = 0.f;
        return; }
    i -= N_H2C;
    if (i < N_PP){ int m=(int)(i>>8), k=(int)(i&255); int b=m&255, t=m>>8;
        P[i] = __float2bfloat16((k < NPOSE) ? poses[((size_t)b*TTOT + t)*NPOSE + k] : 0.f); return; }
    i -= N_PP;
    if (i < N_WIN){ int n=(int)(i>>8), k=(int)(i&255);
        Win[i] = __float2bfloat16((k < NPOSE) ? W_in[(size_t)n*NPOSE+k] : 0.f); return; }
}

// ---------------- one 64x128 bf16 GEMM tile, BK=64, 3-stage cp.async ----------------
// mode 0: LSTM gates (fold-N: col q*1024+bn*32+j), bias, cell update, write h bf16 + c
// mode 1: +bias, bf16 store (ldo)
// mode 2: +bias, relu, bf16 store (ldo)
// mode 3: +bias (+resid cols<135), bf16 s store (ld 256) + optional fp32 pred
__device__ __noinline__ void gemm_phase(
    int mode, int bm, int bnT, int K, int kSplit,
    const __nv_bfloat16* __restrict__ A,  int lda,
    const __nv_bfloat16* __restrict__ A2, int lda2,
    const __nv_bfloat16* __restrict__ Bw, int ldb,
    const float* __restrict__ bias,
    float* __restrict__ cbuf, __nv_bfloat16* __restrict__ hout,
    __nv_bfloat16* __restrict__ ovec, int ldo,
    const float* __restrict__ resid, int resid_stride,
    float* __restrict__ pred, int tstep,
    __nv_bfloat16* smem)
{
    const int tid  = threadIdx.x;
    const int lane = tid & 31;
    const int wid  = tid >> 5;
    const int wm   = wid >> 2;      // 0..1 : 32-row halves
    const int wn   = wid & 3;       // 0..3 : 32-col quarters
    const int tg   = lane >> 2;
    const int ti   = lane & 3;
    const int m0   = bm * 64;
    const int fold = (mode == 0);

    float acc[2][4][4];
    #pragma unroll
    for (int a=0;a<2;a++)
        #pragma unroll
        for (int b=0;b<4;b++)
            #pragma unroll
            for (int e=0;e<4;e++) acc[a][b][e] = 0.f;

    const int nk = K >> 6;

#define LOAD_STAGE(KS, BUF) do { \
    int k0_ = (KS) << 6; \
    __nv_bfloat16* Sa_ = smem + (BUF)*13824; \
    __nv_bfloat16* Sb_ = Sa_ + 4608; \
    _Pragma("unroll") \
    for (int rep=0; rep<2; rep++){ \
        int id = tid + rep*256; int row = id>>3; int cc = (id&7)<<3; int k = k0_ + cc; \
        const __nv_bfloat16* src = (k < kSplit) ? (A + (size_t)(m0+row)*lda + k) \
                                                : (A2 + (size_t)(m0+row)*lda2 + (k - kSplit)); \
        cpa16(Sa_ + row*72 + cc, src); } \
    _Pragma("unroll") \
    for (int rep=0; rep<4; rep++){ \
        int id = tid + rep*256; int row = id>>3; int cc = (id&7)<<3; \
        int ng = fold ? ((row>>5)*1024 + bnT*32 + (row&31)) : (bnT*128 + row); \
        cpa16(Sb_ + row*72 + cc, Bw + (size_t)ng*ldb + k0_ + cc); } \
    asm volatile("cp.async.commit_group;"); \
} while(0)

    LOAD_STAGE(0, 0);
    if (nk > 1) LOAD_STAGE(1, 1);

    for (int ks = 0; ks < nk; ks++){
        if (ks + 1 < nk) asm volatile("cp.async.wait_group 1;");
        else             asm volatile("cp.async.wait_group 0;");
        __syncthreads();

        const __nv_bfloat16* Ab = smem + (ks % 3)*13824;
        const __nv_bfloat16* Bb = Ab + 4608;
        #pragma unroll
        for (int kk = 0; kk < 4; kk++){
            const int kb = kk*16 + 2*ti;
            unsigned af[2][4], bfr[4][2];
            #pragma unroll
            for (int mi = 0; mi < 2; mi++){
                int rb = wm*32 + mi*16 + tg;
                af[mi][0] = ld32s(Ab + rb*72 + kb);
                af[mi][1] = ld32s(Ab + (rb+8)*72 + kb);
                af[mi][2] = ld32s(Ab + rb*72 + kb + 8);
                af[mi][3] = ld32s(Ab + (rb+8)*72 + kb + 8);
            }
            #pragma unroll
            for (int ni = 0; ni < 4; ni++){
                int nb = wn*32 + ni*8 + tg;
                bfr[ni][0] = ld32s(Bb + nb*72 + kb);
                bfr[ni][1] = ld32s(Bb + nb*72 + kb + 8);
            }
            #pragma unroll
            for (int mi = 0; mi < 2; mi++)
                #pragma unroll
                for (int ni = 0; ni < 4; ni++)
                    mma16(acc[mi][ni], af[mi], bfr[ni]);
        }
        __syncthreads();
        if (ks + 2 < nk) LOAD_STAGE(ks + 2, (ks + 2) % 3);
    }
#undef LOAD_STAGE

    if (mode == 0){
        float* Gs = (float*)smem;   // 64 x 132 fp32 overlay (33792 B <= 82944)
        #pragma unroll
        for (int mi = 0; mi < 2; mi++)
            #pragma unroll
            for (int ni = 0; ni < 4; ni++)
                #pragma unroll
                for (int e = 0; e < 4; e++){
                    int rl = wm*32 + mi*16 + tg + ((e>>1)<<3);
                    int cl = wn*32 + ni*8 + 2*ti + (e&1);
                    int gcol = (cl>>5)*1024 + bnT*32 + (cl&31);
                    Gs[rl*132 + cl] = acc[mi][ni][e] + bias[gcol];
                }
        __syncthreads();
        #pragma unroll
        for (int it = tid; it < 64*32; it += 256){
            int mr = it >> 5, jl = it & 31;
            float xi = Gs[mr*132 + jl];
            float xf = Gs[mr*132 + 32 + jl];
            float xg = Gs[mr*132 + 64 + jl];
            float xo = Gs[mr*132 + 96 + jl];
            float ig = 1.f/(1.f+expf(-xi));
            float fg = 1.f/(1.f+expf(-xf));
            float gg = tanhf(xg);
            float og = 1.f/(1.f+expf(-xo));
            int idx = (m0 + mr)*RNN + bnT*32 + jl;
            float cn = fg * cbuf[idx] + ig*gg;
            cbuf[idx] = cn;
            hout[idx] = __float2bfloat16(og * tanhf(cn));
        }
        __syncthreads();
    } else {
        #pragma unroll
        for (int mi = 0; mi < 2; mi++)
            #pragma unroll
            for (int ni = 0; ni < 4; ni++)
                #pragma unroll
                for (int e = 0; e < 4; e++){
                    int rl = wm*32 + mi*16 + tg + ((e>>1)<<3);
                    int cl = wn*32 + ni*8 + 2*ti + (e&1);
                    int mg = m0 + rl;
                    int ng = bnT*128 + cl;
                    float v = acc[mi][ni][e] + bias[ng];
                    if (mode == 1){
                        ovec[(size_t)mg*ldo + ng] = __float2bfloat16(v);
                    } else if (mode == 2){
                        ovec[(size_t)mg*ldo + ng] = __float2bfloat16(fmaxf(v, 0.f));
                    } else {
                        if (ng < NPOSE){
                            if (resid) v += resid[(size_t)mg*resid_stride + ng];
                            if (pred)  pred[((size_t)mg*TGT + tstep)*NPOSE + ng] = v;
                        }
                        ovec[mg*256 + ng] = __float2bfloat16(v);
                    }
                }
        __syncthreads();
    }
}

// ---------------- standalone Z precompute: Z = P @ Win^T + b_in ----------------
__global__ void __launch_bounds__(256) zgemm_kernel(const float* __restrict__ b_in)
{
    extern __shared__ __nv_bfloat16 smem[];
    const __nv_bfloat16* P   = (const __nv_bfloat16*)g_P_;
    const __nv_bfloat16* Win = (const __nv_bfloat16*)g_Win_;
    __nv_bfloat16* Z         = (__nv_bfloat16*)g_Z_;
    gemm_phase(1, blockIdx.x, blockIdx.y, 256, 256,
               P, 256, P, 256, Win, 256, b_in,
               nullptr, nullptr, Z, 256, nullptr, 0, nullptr, 0, smem);
}

// ---------------- grid barrier ----------------
__device__ __forceinline__ void gridbar(unsigned target){
    __syncthreads();
    if (threadIdx.x == 0){
        __threadfence();
        atomicAdd(&g_bar, 1u);
        while (*(volatile unsigned*)&g_bar < target) __nanosleep(32);
    }
    __syncthreads();
}

// ---------------- persistent recurrence kernel (grid = 128 CTAs) ----------------
__global__ void __launch_bounds__(256, 1) persist_kernel(
    const float* __restrict__ poses, const float* __restrict__ b_in,
    float* __restrict__ out)
{
    extern __shared__ __nv_bfloat16 smem[];
    const int ct = blockIdx.x;

    __nv_bfloat16* H[2] = {(__nv_bfloat16*)g_h0_, (__nv_bfloat16*)g_h1_};
    const __nv_bfloat16* Z   = (const __nv_bfloat16*)g_Z_;
    const __nv_bfloat16* Wc  = (const __nv_bfloat16*)g_Wcat_;
    const __nv_bfloat16* W1  = (const __nv_bfloat16*)g_Wr1_;
    const __nv_bfloat16* W2  = (const __nv_bfloat16*)g_Wr2_;
    const __nv_bfloat16* Win = (const __nv_bfloat16*)g_Win_;
    __nv_bfloat16* R1 = (__nv_bfloat16*)g_r1_;
    __nv_bfloat16* S  = (__nv_bfloat16*)g_s_;
    __nv_bfloat16* ZD = (__nv_bfloat16*)g_zd_;

    unsigned ep = 0;
    int p = 0;

    // ---- encoder: 119 fused gate steps ----
    for (int t = 0; t < ENCS; t++){
        gemm_phase(0, ct>>5, ct&31, KDEC, 1024,
                   H[p], RNN, Z + (size_t)t*256*256, 256, Wc, KDEC,
                   g_biasg, g_c, H[p^1], nullptr, 0, nullptr, 0, nullptr, 0, smem);
        p ^= 1;
        ep++; gridbar(ep*NCTA);
    }
    // ---- encoder head: r1 = relu(h@W1^T+b) ; s0 = r1@W2^T + b + poses[:,118] ----
    if (ct < 32)
        gemm_phase(2, ct>>3, ct&7, 1024, 1024, H[p], RNN, H[p], RNN, W1, 1024,
                   g_br1, nullptr, nullptr, R1, 1024, nullptr, 0, nullptr, 0, smem);
    ep++; gridbar(ep*NCTA);
    if (ct < 8)
        gemm_phase(3, ct>>1, ct&1, 1024, 1024, R1, 1024, R1, 1024, W2, 1024,
                   g_br2, nullptr, nullptr, S, 256,
                   poses + 118*NPOSE, TTOT*NPOSE, nullptr, 0, smem);
    ep++; gridbar(ep*NCTA);

    // ---- decoder: 24 autoregressive steps ----
    for (int t = 0; t < TGT; t++){
        if (ct < 8)
            gemm_phase(1, ct>>1, ct&1, 256, 256, S, 256, S, 256, Win, 256,
                       b_in, nullptr, nullptr, ZD, 256, nullptr, 0, nullptr, 0, smem);
        ep++; gridbar(ep*NCTA);
        gemm_phase(0, ct>>5, ct&31, KDEC, 1024,
                   H[p], RNN, ZD, 256, Wc, KDEC,
                   g_biasg, g_c, H[p^1], nullptr, 0, nullptr, 0, nullptr, 0, smem);
        p ^= 1;
        ep++; gridbar(ep*NCTA);
        if (ct < 32)
            gemm_phase(2, ct>>3, ct&7, 1024, 1024, H[p], RNN, H[p], RNN, W1, 1024,
                       g_br1, nullptr, nullptr, R1, 1024, nullptr, 0, nullptr, 0, smem);
        ep++; gridbar(ep*NCTA);
        if (ct < 8)
            gemm_phase(3, ct>>1, ct&1, 1024, 1024, R1, 1024, R1, 1024, W2, 1024,
                       g_br2, nullptr, nullptr, S, 256,
                       (t == 0) ? (poses + 119*NPOSE) : nullptr, TTOT*NPOSE, out, t, smem);
        ep++; gridbar(ep*NCTA);
    }
}

// ---------------- host launch sequence (graph-capturable) ----------------
extern "C" void kernel_launch(void* const* d_in, const int* in_sizes, int n_in,
                              void* d_out, int out_size)
{
    const float* poses = (const float*)d_in[0];
    const float* W_in  = (const float*)d_in[1];
    const float* b_in  = (const float*)d_in[2];
    const float* W_ih  = (const float*)d_in[3];
    const float* W_hh  = (const float*)d_in[4];
    const float* b_ih  = (const float*)d_in[5];
    const float* b_hh  = (const float*)d_in[6];
    const float* W_r1  = (const float*)d_in[7];
    const float* b_r1  = (const float*)d_in[8];
    const float* W_r2  = (const float*)d_in[9];
    const float* b_r2  = (const float*)d_in[10];
    float* out = (float*)d_out;

    static int attr_done = 0;
    if (!attr_done){
        cudaFuncSetAttribute(zgemm_kernel,   cudaFuncAttributeMaxDynamicSharedMemorySize, SMEM_BYTES);
        cudaFuncSetAttribute(persist_kernel, cudaFuncAttributeMaxDynamicSharedMemorySize, SMEM_BYTES);
        attr_done = 1;
    }

    prep_kernel<<<(NTOT + 255)/256, 256>>>(poses, W_in, W_ih, W_hh, b_ih, b_hh,
                                           W_r1, b_r1, W_r2, b_r2);
    zgemm_kernel<<<dim3(MZ/64, 2), 256, SMEM_BYTES>>>(b_in);
    persist_kernel<<<NCTA, 256, SMEM_BYTES>>>(poses, b_in, out);
}